// round 8
// baseline (speedup 1.0000x reference)
#include <cuda_runtime.h>
#include <cuda_fp16.h>
#include <cstdint>
#include <cstddef>

// ============================================================================
// MoE FFN, sm_103 baseline. fp16 mma.sync m16n8k16 + ldmatrix.x4, BK=64.
// R8 = R7 with epilogue-exchange alignment fix (stride 33 -> 34 floats).
// 512-thread CTA (16 warps = 4/SMSP), CTA tile 256x128, warp tile 64x32,
// 3-stage cp.async.
//   PRE  : h -> fp16; W1,W2 -> fp16 + transpose to [E][N][K]
//   G1A  : act = fp16(up * relu(gate))   (fused epilogue, 64 act cols/CTA)
//   GEMM2: out = act @ W2t
// ============================================================================

#define KD 2048

__device__ __half g_act[8192ull * 2048ull];          //  33 MB
__device__ __half g_hh [8192ull * 2048ull];          //  33 MB
__device__ __half g_w1t[8ull * 4096ull * 2048ull];   // 134 MB W1^T [E][N][K]
__device__ __half g_w2t[8ull * 2048ull * 2048ull];   //  67 MB W2^T [E][N][K]

static constexpr int STRIDE_H = 72;                      // halves: 64 + 8 pad
static constexpr int ROW_B    = STRIDE_H * 2;            // 144 bytes
static constexpr int A_TILE_B = 256 * ROW_B;             // 36864
static constexpr int B_TILE_B = 128 * ROW_B;             // 18432
static constexpr int STAGE_B  = A_TILE_B + B_TILE_B;     // 55296
static constexpr int STAGES   = 3;
static constexpr int SMEM_TOTAL = STAGE_B * STAGES;      // 165888
static constexpr int EX_STRIDE = 34;                     // f32, even => 8B align

__device__ __forceinline__ uint32_t smem_u32(const void* p) {
    uint32_t a;
    asm("{ .reg .u64 t; cvta.to.shared.u64 t, %1; cvt.u32.u64 %0, t; }"
        : "=r"(a) : "l"(p));
    return a;
}

#define CP16(d, s) asm volatile("cp.async.cg.shared.global [%0], [%1], 16;" \
                                :: "r"(d), "l"(s))
#define CP_COMMIT() asm volatile("cp.async.commit_group;" ::: "memory")
#define CP_WAITG(n) asm volatile("cp.async.wait_group %0;" :: "n"(n) : "memory")

#define LDSM_X4(r0, r1, r2, r3, a) asm volatile(                             \
    "ldmatrix.sync.aligned.m8n8.x4.shared.b16 {%0,%1,%2,%3}, [%4];"          \
    : "=r"(r0), "=r"(r1), "=r"(r2), "=r"(r3) : "r"(a))

__device__ __forceinline__ void mma_f16(float c[4], const uint32_t a[4],
                                        const uint32_t b[2]) {
    asm volatile(
        "mma.sync.aligned.m16n8k16.row.col.f32.f16.f16.f32 "
        "{%0,%1,%2,%3}, {%4,%5,%6,%7}, {%8,%9}, {%0,%1,%2,%3};"
        : "+f"(c[0]), "+f"(c[1]), "+f"(c[2]), "+f"(c[3])
        : "r"(a[0]), "r"(a[1]), "r"(a[2]), "r"(a[3]), "r"(b[0]), "r"(b[1]));
}

// per-lane ldmatrix byte offsets (16 rows x 16 halves per x4)
__device__ __forceinline__ uint32_t ldsm_offA(int lane) {
    const int r8 = lane & 7;
    return (uint32_t)(((((lane >> 3) & 1) * 8 + r8) * STRIDE_H
                       + (lane >> 4) * 8) * 2);
}
__device__ __forceinline__ uint32_t ldsm_offB(int lane) {
    const int r8 = lane & 7;
    return (uint32_t)((((lane >> 4) * 8 + r8) * STRIDE_H
                       + ((lane >> 3) & 1) * 8) * 2);
}

// fragment load + MMA for one ks step (warp tile 64x32)
#define KS_STEP(ks, st, abase, bbase, acc) do {                              \
    const uint32_t _ko = (uint32_t)((ks) * 32);                              \
    uint32_t _af[4][4], _bf[4][2];                                           \
    _Pragma("unroll")                                                        \
    for (int _mi = 0; _mi < 4; _mi++)                                        \
        LDSM_X4(_af[_mi][0], _af[_mi][1], _af[_mi][2], _af[_mi][3],          \
                (st) + (abase) + _ko + (uint32_t)(_mi * 16 * ROW_B));        \
    _Pragma("unroll")                                                        \
    for (int _b = 0; _b < 2; _b++)                                           \
        LDSM_X4(_bf[2 * _b][0], _bf[2 * _b][1],                              \
                _bf[2 * _b + 1][0], _bf[2 * _b + 1][1],                      \
                (st) + (bbase) + _ko + (uint32_t)(_b * 16 * ROW_B));         \
    _Pragma("unroll")                                                        \
    for (int _mi = 0; _mi < 4; _mi++)                                        \
        _Pragma("unroll")                                                    \
        for (int _ni = 0; _ni < 4; _ni++)                                    \
            mma_f16(acc[_mi][_ni], _af[_mi], _bf[_ni]);                      \
} while (0)

// ---------------------------------------------------------------------------
// GEMM1 fused with activation. CTA: 256 tokens x 64 act cols.
// B tile rows 0-63 = gate n's, rows 64-127 = up n's (same 64 n's).
// Warps: wm=wid&3 (4 x 64 tokens), wn=wid>>2: wn<2 gate half, wn>=2 up half.
// ---------------------------------------------------------------------------
__global__ void __launch_bounds__(512, 1)
gemm1_act(const __half* __restrict__ X, const __half* __restrict__ W1t,
          __half* __restrict__ Act)
{
    extern __shared__ __align__(16) char smem[];
    const int tid = threadIdx.x;
    const int wid = tid >> 5, lane = tid & 31;
    const int g = lane >> 2, tg = lane & 3;
    const int wm = wid & 3, wn = wid >> 2;
    const int nt = blockIdx.x, tt = blockIdx.y, e = blockIdx.z;

    const __half* Ag = X + (size_t)(e * 1024 + tt * 256) * KD;
    const __half* BgGate = W1t + (size_t)e * 4096 * KD + (size_t)(nt * 64) * KD;
    const __half* BgUp   = BgGate + (size_t)2048 * KD;
    const uint32_t sbase = smem_u32(smem);

    const int cr = tid >> 3, cc = tid & 7;       // 64 rows/pass, 8 chunks
    const uint32_t cdst = (uint32_t)(cr * ROW_B + cc * 16);

    auto load_stage = [&](int buf, int kt) {
        const uint32_t sa = sbase + (uint32_t)buf * STAGE_B;
        const uint32_t sb = sa + A_TILE_B;
        const __half* a = Ag + kt * 64;
#pragma unroll
        for (int j = 0; j < 4; j++)
            CP16(sa + cdst + (uint32_t)(j * 64 * ROW_B),
                 a + (size_t)(cr + j * 64) * KD + cc * 8);
#pragma unroll
        for (int j = 0; j < 2; j++) {
            const int rb = cr + j * 64;
            const __half* b = (rb < 64 ? BgGate + (size_t)rb * KD
                                       : BgUp + (size_t)(rb - 64) * KD)
                            + kt * 64 + cc * 8;
            CP16(sb + cdst + (uint32_t)(j * 64 * ROW_B), b);
        }
        CP_COMMIT();
    };

    const uint32_t abase = (uint32_t)(wm * 64 * ROW_B) + ldsm_offA(lane);
    const uint32_t bbase = (uint32_t)(wn * 32 * ROW_B) + ldsm_offB(lane)
                         + A_TILE_B;

    float acc[4][4][4];
#pragma unroll
    for (int mi = 0; mi < 4; mi++)
#pragma unroll
        for (int ni = 0; ni < 4; ni++)
#pragma unroll
            for (int q = 0; q < 4; q++) acc[mi][ni][q] = 0.f;

    load_stage(0, 0);
    load_stage(1, 1);

    constexpr int NKT = KD / 64;   // 32
    for (int kt = 0; kt < NKT; kt++) {
        if (kt == NKT - 1) { CP_WAITG(0); } else { CP_WAITG(1); }
        __syncthreads();
        if (kt + 2 < NKT) load_stage((kt + 2) % STAGES, kt + 2);

        const uint32_t st = sbase + (uint32_t)((kt % STAGES) * STAGE_B);
#pragma unroll
        for (int ks = 0; ks < 4; ks++)
            KS_STEP(ks, st, abase, bbase, acc);
    }

    // ---- fused act epilogue ---------------------------------------------
    __syncthreads();
    // exchange: [wm(4)][half(2)][64 rows][EX_STRIDE cols] f32
    float* ex = reinterpret_cast<float*>(smem)
              + (size_t)(wm * 2 + (wn & 1)) * (64 * EX_STRIDE);
    if (wn >= 2) {                          // up warps publish
#pragma unroll
        for (int mi = 0; mi < 4; mi++) {
            const int r0 = mi * 16 + g;
#pragma unroll
            for (int ni = 0; ni < 4; ni++) {
                const int cb = ni * 8 + tg * 2;
                *reinterpret_cast<float2*>(ex + r0 * EX_STRIDE + cb) =
                    make_float2(acc[mi][ni][0], acc[mi][ni][1]);
                *reinterpret_cast<float2*>(ex + (r0 + 8) * EX_STRIDE + cb) =
                    make_float2(acc[mi][ni][2], acc[mi][ni][3]);
            }
        }
    }
    __syncthreads();
    if (wn < 2) {                           // gate warps combine + store
        __half* Og = Act + (size_t)(e * 1024 + tt * 256 + wm * 64) * 2048
                   + nt * 64 + wn * 32;
#pragma unroll
        for (int mi = 0; mi < 4; mi++) {
            const int r0 = mi * 16 + g;
#pragma unroll
            for (int ni = 0; ni < 4; ni++) {
                const int cb = ni * 8 + tg * 2;
                const float2 ulo =
                    *reinterpret_cast<float2*>(ex + r0 * EX_STRIDE + cb);
                const float2 uhi =
                    *reinterpret_cast<float2*>(ex + (r0 + 8) * EX_STRIDE + cb);
                __half2 lo = __floats2half2_rn(
                    ulo.x * fmaxf(acc[mi][ni][0], 0.f),
                    ulo.y * fmaxf(acc[mi][ni][1], 0.f));
                __half2 hi = __floats2half2_rn(
                    uhi.x * fmaxf(acc[mi][ni][2], 0.f),
                    uhi.y * fmaxf(acc[mi][ni][3], 0.f));
                *reinterpret_cast<uint32_t*>(Og + (size_t)r0 * 2048 + cb) =
                    *reinterpret_cast<uint32_t*>(&lo);
                *reinterpret_cast<uint32_t*>(Og + (size_t)(r0 + 8) * 2048 + cb) =
                    *reinterpret_cast<uint32_t*>(&hi);
            }
        }
    }
}

// ---------------------------------------------------------------------------
// GEMM2: plain 256x128 CTA tile, fp32 out.
// ---------------------------------------------------------------------------
__global__ void __launch_bounds__(512, 1)
gemm2(const __half* __restrict__ X, const __half* __restrict__ Wt,
      float* __restrict__ C)
{
    extern __shared__ __align__(16) char smem[];
    const int tid = threadIdx.x;
    const int wid = tid >> 5, lane = tid & 31;
    const int g = lane >> 2, tg = lane & 3;
    const int wm = wid & 3, wn = wid >> 2;
    const int nt = blockIdx.x, tt = blockIdx.y, e = blockIdx.z;
    constexpr int WN = 2048;

    const __half* Ag = X + (size_t)(e * 1024 + tt * 256) * KD;
    const __half* Bg = Wt + (size_t)e * WN * KD + (size_t)(nt * 128) * KD;
    const uint32_t sbase = smem_u32(smem);

    const int cr = tid >> 3, cc = tid & 7;
    const uint32_t cdst = (uint32_t)(cr * ROW_B + cc * 16);

    auto load_stage = [&](int buf, int kt) {
        const uint32_t sa = sbase + (uint32_t)buf * STAGE_B;
        const uint32_t sb = sa + A_TILE_B;
        const __half* a = Ag + kt * 64;
        const __half* b = Bg + kt * 64;
#pragma unroll
        for (int j = 0; j < 4; j++)
            CP16(sa + cdst + (uint32_t)(j * 64 * ROW_B),
                 a + (size_t)(cr + j * 64) * KD + cc * 8);
#pragma unroll
        for (int j = 0; j < 2; j++)
            CP16(sb + cdst + (uint32_t)(j * 64 * ROW_B),
                 b + (size_t)(cr + j * 64) * KD + cc * 8);
        CP_COMMIT();
    };

    const uint32_t abase = (uint32_t)(wm * 64 * ROW_B) + ldsm_offA(lane);
    const uint32_t bbase = (uint32_t)(wn * 32 * ROW_B) + ldsm_offB(lane)
                         + A_TILE_B;

    float acc[4][4][4];
#pragma unroll
    for (int mi = 0; mi < 4; mi++)
#pragma unroll
        for (int ni = 0; ni < 4; ni++)
#pragma unroll
            for (int q = 0; q < 4; q++) acc[mi][ni][q] = 0.f;

    load_stage(0, 0);
    load_stage(1, 1);

    constexpr int NKT = KD / 64;   // 32
    for (int kt = 0; kt < NKT; kt++) {
        if (kt == NKT - 1) { CP_WAITG(0); } else { CP_WAITG(1); }
        __syncthreads();
        if (kt + 2 < NKT) load_stage((kt + 2) % STAGES, kt + 2);

        const uint32_t st = sbase + (uint32_t)((kt % STAGES) * STAGE_B);
#pragma unroll
        for (int ks = 0; ks < 4; ks++)
            KS_STEP(ks, st, abase, bbase, acc);
    }

    float* Cg = C + (size_t)(e * 1024 + tt * 256) * WN + nt * 128;
#pragma unroll
    for (int mi = 0; mi < 4; mi++) {
        const int r0 = wm * 64 + mi * 16 + g;
#pragma unroll
        for (int ni = 0; ni < 4; ni++) {
            const int cb = wn * 32 + ni * 8 + tg * 2;
            float2 lo = make_float2(acc[mi][ni][0], acc[mi][ni][1]);
            float2 hi = make_float2(acc[mi][ni][2], acc[mi][ni][3]);
            *reinterpret_cast<float2*>(Cg + (size_t)r0 * WN + cb) = lo;
            *reinterpret_cast<float2*>(Cg + (size_t)(r0 + 8) * WN + cb) = hi;
        }
    }
}

__global__ void __launch_bounds__(256)
round_f16_k(__half* __restrict__ dst, const float* __restrict__ src)
{
    const size_t i = ((size_t)blockIdx.x * blockDim.x + threadIdx.x) * 4;
    const float4 v = *reinterpret_cast<const float4*>(src + i);
    __half2 lo = __floats2half2_rn(v.x, v.y);
    __half2 hi = __floats2half2_rn(v.z, v.w);
    uint2 o = make_uint2(*reinterpret_cast<uint32_t*>(&lo),
                         *reinterpret_cast<uint32_t*>(&hi));
    *reinterpret_cast<uint2*>(dst + i) = o;
}

// src [E][K][N] f32 -> dst [E][N][K] fp16. block (32,8).
__global__ void __launch_bounds__(256)
transpose_f16(__half* __restrict__ dst, const float* __restrict__ src,
              int K, int N)
{
    __shared__ float tile[32][33];
    const int tx = threadIdx.x, ty = threadIdx.y;
    const int n0 = blockIdx.x * 32, k0 = blockIdx.y * 32, e = blockIdx.z;
    const float* s = src + (size_t)e * K * N;
    __half* d = dst + (size_t)e * N * K;
#pragma unroll
    for (int j = 0; j < 4; j++)
        tile[ty + 8 * j][tx] = s[(size_t)(k0 + ty + 8 * j) * N + n0 + tx];
    __syncthreads();
#pragma unroll
    for (int j = 0; j < 4; j++)
        d[(size_t)(n0 + ty + 8 * j) * K + k0 + tx] =
            __float2half_rn(tile[tx][ty + 8 * j]);
}

extern "C" void kernel_launch(void* const* d_in, const int* in_sizes, int n_in,
                              void* d_out, int out_size) {
    (void)in_sizes; (void)n_in; (void)out_size;
    const float* h  = (const float*)d_in[0];
    const float* w1 = (const float*)d_in[1];
    const float* w2 = (const float*)d_in[2];
    float* out = (float*)d_out;

    __half *act, *hh, *w1t, *w2t;
    cudaGetSymbolAddress((void**)&act, g_act);
    cudaGetSymbolAddress((void**)&hh,  g_hh);
    cudaGetSymbolAddress((void**)&w1t, g_w1t);
    cudaGetSymbolAddress((void**)&w2t, g_w2t);

    cudaFuncSetAttribute(gemm1_act,
                         cudaFuncAttributeMaxDynamicSharedMemorySize, SMEM_TOTAL);
    cudaFuncSetAttribute(gemm2,
                         cudaFuncAttributeMaxDynamicSharedMemorySize, SMEM_TOTAL);

    round_f16_k<<<(8192ull * 2048 / 4) / 256, 256>>>(hh, h);
    transpose_f16<<<dim3(4096 / 32, 2048 / 32, 8), dim3(32, 8)>>>(w1t, w1, 2048, 4096);
    transpose_f16<<<dim3(2048 / 32, 2048 / 32, 8), dim3(32, 8)>>>(w2t, w2, 2048, 2048);

    gemm1_act<<<dim3(32, 4, 8), 512, SMEM_TOTAL>>>(hh, w1t, act);
    gemm2<<<dim3(16, 4, 8), 512, SMEM_TOTAL>>>(act, w2t, out);
}

// round 9
// speedup vs baseline: 1.0932x; 1.0932x over previous
#include <cuda_runtime.h>
#include <cuda_fp16.h>
#include <cstdint>
#include <cstddef>

// ============================================================================
// MoE FFN, sm_103 baseline. fp16 mma.sync m16n8k16 + ldmatrix.x4, BK=64,
// 3-stage cp.async. R9: R5 mainloop (128-thr CTA, warp 64x64, 2 CTA/SM,
// no reg double-buffer) + R6 fused act epilogue + vectorized transpose.
//   PRE  : h -> fp16; W1,W2 -> fp16 + transpose to [E][N][K]
//   G1A  : act = fp16(up * relu(gate))   (fused epilogue)
//   GEMM2: out = act @ W2t
// ============================================================================

#define KD 2048

__device__ __half g_act[8192ull * 2048ull];          //  33 MB
__device__ __half g_hh [8192ull * 2048ull];          //  33 MB
__device__ __half g_w1t[8ull * 4096ull * 2048ull];   // 134 MB W1^T [E][N][K]
__device__ __half g_w2t[8ull * 2048ull * 2048ull];   //  67 MB W2^T [E][N][K]

static constexpr int STRIDE_H = 72;                      // halves: 64 + 8 pad
static constexpr int ROW_B    = STRIDE_H * 2;            // 144 bytes
static constexpr int TILE_B   = 128 * ROW_B;             // 18432
static constexpr int STAGE_B  = 2 * TILE_B;              // 36864
static constexpr int STAGES   = 3;
static constexpr int SMEM_TOTAL = STAGE_B * STAGES;      // 110592

__device__ __forceinline__ uint32_t smem_u32(const void* p) {
    uint32_t a;
    asm("{ .reg .u64 t; cvta.to.shared.u64 t, %1; cvt.u32.u64 %0, t; }"
        : "=r"(a) : "l"(p));
    return a;
}

#define CP16(d, s) asm volatile("cp.async.cg.shared.global [%0], [%1], 16;" \
                                :: "r"(d), "l"(s))
#define CP_COMMIT() asm volatile("cp.async.commit_group;" ::: "memory")
#define CP_WAITG(n) asm volatile("cp.async.wait_group %0;" :: "n"(n) : "memory")

#define LDSM_X4(r0, r1, r2, r3, a) asm volatile(                             \
    "ldmatrix.sync.aligned.m8n8.x4.shared.b16 {%0,%1,%2,%3}, [%4];"          \
    : "=r"(r0), "=r"(r1), "=r"(r2), "=r"(r3) : "r"(a))

__device__ __forceinline__ void mma_f16(float c[4], const uint32_t a[4],
                                        const uint32_t b[2]) {
    asm volatile(
        "mma.sync.aligned.m16n8k16.row.col.f32.f16.f16.f32 "
        "{%0,%1,%2,%3}, {%4,%5,%6,%7}, {%8,%9}, {%0,%1,%2,%3};"
        : "+f"(c[0]), "+f"(c[1]), "+f"(c[2]), "+f"(c[3])
        : "r"(a[0]), "r"(a[1]), "r"(a[2]), "r"(a[3]), "r"(b[0]), "r"(b[1]));
}

// per-lane ldmatrix byte offsets
__device__ __forceinline__ uint32_t ldsm_offA(int lane) {
    const int r8 = lane & 7;
    return (uint32_t)(((((lane >> 3) & 1) * 8 + r8) * STRIDE_H
                       + (lane >> 4) * 8) * 2);
}
__device__ __forceinline__ uint32_t ldsm_offB(int lane) {
    const int r8 = lane & 7;
    return (uint32_t)((((lane >> 4) * 8 + r8) * STRIDE_H
                       + ((lane >> 3) & 1) * 8) * 2);
}

// one ks step, warp tile 64x64: 4 A-LDSM.x4 + 4 B-LDSM.x4 + 32 MMA
#define KS_STEP64(ks, st, abase, bbase, acc) do {                            \
    const uint32_t _ko = (uint32_t)((ks) * 32);                              \
    uint32_t _af[4][4], _bf[8][2];                                           \
    _Pragma("unroll")                                                        \
    for (int _mi = 0; _mi < 4; _mi++)                                        \
        LDSM_X4(_af[_mi][0], _af[_mi][1], _af[_mi][2], _af[_mi][3],          \
                (st) + (abase) + _ko + (uint32_t)(_mi * 16 * ROW_B));        \
    _Pragma("unroll")                                                        \
    for (int _b = 0; _b < 4; _b++)                                           \
        LDSM_X4(_bf[2 * _b][0], _bf[2 * _b][1],                              \
                _bf[2 * _b + 1][0], _bf[2 * _b + 1][1],                      \
                (st) + (bbase) + _ko + (uint32_t)(_b * 16 * ROW_B));         \
    _Pragma("unroll")                                                        \
    for (int _mi = 0; _mi < 4; _mi++)                                        \
        _Pragma("unroll")                                                    \
        for (int _ni = 0; _ni < 8; _ni++)                                    \
            mma_f16(acc[_mi][_ni], _af[_mi], _bf[_ni]);                      \
} while (0)

// ---------------------------------------------------------------------------
// GEMM1 fused with activation. CTA: 128 tokens x 64 act cols.
// B tile rows 0-63 = gate n's, 64-127 = up n's. wn=0 gate, wn=1 up.
// ---------------------------------------------------------------------------
__global__ void __launch_bounds__(128, 2)
gemm1_act(const __half* __restrict__ X, const __half* __restrict__ W1t,
          __half* __restrict__ Act)
{
    extern __shared__ __align__(16) char smem[];
    const int tid = threadIdx.x;
    const int wid = tid >> 5, lane = tid & 31;
    const int g = lane >> 2, tg = lane & 3;
    const int wm = wid & 1, wn = wid >> 1;
    const int nt = blockIdx.x, tt = blockIdx.y, e = blockIdx.z;

    const __half* Ag = X + (size_t)(e * 1024 + tt * 128) * KD;
    const __half* BgGate = W1t + (size_t)e * 4096 * KD + (size_t)(nt * 64) * KD;
    const __half* BgUp   = BgGate + (size_t)2048 * KD;
    const uint32_t sbase = smem_u32(smem);

    const int cr = tid >> 3, cc = tid & 7;       // 16 rows/pass, 8 chunks
    const uint32_t cdst = (uint32_t)(cr * ROW_B + cc * 16);

    // hoisted per-thread B source pointers (gate rows 0-63, up rows 64-127)
    const __half* bsrc[8];
#pragma unroll
    for (int j = 0; j < 8; j++) {
        const int rb = cr + j * 16;
        bsrc[j] = (rb < 64 ? BgGate + (size_t)rb * KD
                           : BgUp + (size_t)(rb - 64) * KD) + cc * 8;
    }

    auto load_stage = [&](int buf, int kt) {
        const uint32_t sa = sbase + (uint32_t)buf * STAGE_B;
        const uint32_t sb = sa + TILE_B;
        const __half* a = Ag + kt * 64;
#pragma unroll
        for (int j = 0; j < 8; j++)
            CP16(sa + cdst + (uint32_t)(j * 16 * ROW_B),
                 a + (size_t)(cr + j * 16) * KD + cc * 8);
#pragma unroll
        for (int j = 0; j < 8; j++)
            CP16(sb + cdst + (uint32_t)(j * 16 * ROW_B), bsrc[j] + kt * 64);
        CP_COMMIT();
    };

    const uint32_t abase = (uint32_t)(wm * 64 * ROW_B) + ldsm_offA(lane);
    const uint32_t bbase = (uint32_t)(wn * 64 * ROW_B) + ldsm_offB(lane)
                         + TILE_B;

    float acc[4][8][4];
#pragma unroll
    for (int mi = 0; mi < 4; mi++)
#pragma unroll
        for (int ni = 0; ni < 8; ni++)
#pragma unroll
            for (int q = 0; q < 4; q++) acc[mi][ni][q] = 0.f;

    load_stage(0, 0);
    load_stage(1, 1);

    constexpr int NKT = KD / 64;   // 32
    for (int kt = 0; kt < NKT; kt++) {
        if (kt == NKT - 1) { CP_WAITG(0); } else { CP_WAITG(1); }
        __syncthreads();
        if (kt + 2 < NKT) load_stage((kt + 2) % STAGES, kt + 2);

        const uint32_t st = sbase + (uint32_t)((kt % STAGES) * STAGE_B);
#pragma unroll
        for (int ks = 0; ks < 4; ks++)
            KS_STEP64(ks, st, abase, bbase, acc);
    }

    // ---- fused act epilogue (stride 66 f32, 8B-aligned float2) ----------
    __syncthreads();
    float* ex = reinterpret_cast<float*>(smem) + wm * (64 * 66);
    if (wn == 1) {                         // up warps publish
#pragma unroll
        for (int mi = 0; mi < 4; mi++) {
            const int r0 = mi * 16 + g;
#pragma unroll
            for (int ni = 0; ni < 8; ni++) {
                const int cb = ni * 8 + tg * 2;
                *reinterpret_cast<float2*>(ex + r0 * 66 + cb) =
                    make_float2(acc[mi][ni][0], acc[mi][ni][1]);
                *reinterpret_cast<float2*>(ex + (r0 + 8) * 66 + cb) =
                    make_float2(acc[mi][ni][2], acc[mi][ni][3]);
            }
        }
    }
    __syncthreads();
    if (wn == 0) {                         // gate warps combine + store
        __half* Og = Act + (size_t)(e * 1024 + tt * 128 + wm * 64) * 2048
                   + nt * 64;
#pragma unroll
        for (int mi = 0; mi < 4; mi++) {
            const int r0 = mi * 16 + g;
#pragma unroll
            for (int ni = 0; ni < 8; ni++) {
                const int cb = ni * 8 + tg * 2;
                const float2 ulo = *reinterpret_cast<float2*>(ex + r0 * 66 + cb);
                const float2 uhi =
                    *reinterpret_cast<float2*>(ex + (r0 + 8) * 66 + cb);
                __half2 lo = __floats2half2_rn(
                    ulo.x * fmaxf(acc[mi][ni][0], 0.f),
                    ulo.y * fmaxf(acc[mi][ni][1], 0.f));
                __half2 hi = __floats2half2_rn(
                    uhi.x * fmaxf(acc[mi][ni][2], 0.f),
                    uhi.y * fmaxf(acc[mi][ni][3], 0.f));
                *reinterpret_cast<uint32_t*>(Og + (size_t)r0 * 2048 + cb) =
                    *reinterpret_cast<uint32_t*>(&lo);
                *reinterpret_cast<uint32_t*>(Og + (size_t)(r0 + 8) * 2048 + cb) =
                    *reinterpret_cast<uint32_t*>(&hi);
            }
        }
    }
}

// ---------------------------------------------------------------------------
// GEMM2: plain 128x128 CTA tile, fp32 out.
// ---------------------------------------------------------------------------
__global__ void __launch_bounds__(128, 2)
gemm2(const __half* __restrict__ X, const __half* __restrict__ Wt,
      float* __restrict__ C)
{
    extern __shared__ __align__(16) char smem[];
    const int tid = threadIdx.x;
    const int wid = tid >> 5, lane = tid & 31;
    const int g = lane >> 2, tg = lane & 3;
    const int wm = wid & 1, wn = wid >> 1;
    const int nt = blockIdx.x, tt = blockIdx.y, e = blockIdx.z;
    constexpr int WN = 2048;

    const __half* Ag = X + (size_t)(e * 1024 + tt * 128) * KD;
    const __half* Bg = Wt + (size_t)e * WN * KD + (size_t)(nt * 128) * KD;
    const uint32_t sbase = smem_u32(smem);

    const int cr = tid >> 3, cc = tid & 7;
    const uint32_t cdst = (uint32_t)(cr * ROW_B + cc * 16);

    auto load_stage = [&](int buf, int kt) {
        const uint32_t sa = sbase + (uint32_t)buf * STAGE_B;
        const uint32_t sb = sa + TILE_B;
        const __half* a = Ag + kt * 64;
        const __half* b = Bg + kt * 64;
#pragma unroll
        for (int j = 0; j < 8; j++)
            CP16(sa + cdst + (uint32_t)(j * 16 * ROW_B),
                 a + (size_t)(cr + j * 16) * KD + cc * 8);
#pragma unroll
        for (int j = 0; j < 8; j++)
            CP16(sb + cdst + (uint32_t)(j * 16 * ROW_B),
                 b + (size_t)(cr + j * 16) * KD + cc * 8);
        CP_COMMIT();
    };

    const uint32_t abase = (uint32_t)(wm * 64 * ROW_B) + ldsm_offA(lane);
    const uint32_t bbase = (uint32_t)(wn * 64 * ROW_B) + ldsm_offB(lane)
                         + TILE_B;

    float acc[4][8][4];
#pragma unroll
    for (int mi = 0; mi < 4; mi++)
#pragma unroll
        for (int ni = 0; ni < 8; ni++)
#pragma unroll
            for (int q = 0; q < 4; q++) acc[mi][ni][q] = 0.f;

    load_stage(0, 0);
    load_stage(1, 1);

    constexpr int NKT = KD / 64;   // 32
    for (int kt = 0; kt < NKT; kt++) {
        if (kt == NKT - 1) { CP_WAITG(0); } else { CP_WAITG(1); }
        __syncthreads();
        if (kt + 2 < NKT) load_stage((kt + 2) % STAGES, kt + 2);

        const uint32_t st = sbase + (uint32_t)((kt % STAGES) * STAGE_B);
#pragma unroll
        for (int ks = 0; ks < 4; ks++)
            KS_STEP64(ks, st, abase, bbase, acc);
    }

    float* Cg = C + (size_t)(e * 1024 + tt * 128) * WN + nt * 128;
#pragma unroll
    for (int mi = 0; mi < 4; mi++) {
        const int r0 = wm * 64 + mi * 16 + g;
#pragma unroll
        for (int ni = 0; ni < 8; ni++) {
            const int cb = wn * 64 + ni * 8 + tg * 2;
            float2 lo = make_float2(acc[mi][ni][0], acc[mi][ni][1]);
            float2 hi = make_float2(acc[mi][ni][2], acc[mi][ni][3]);
            *reinterpret_cast<float2*>(Cg + (size_t)r0 * WN + cb) = lo;
            *reinterpret_cast<float2*>(Cg + (size_t)(r0 + 8) * WN + cb) = hi;
        }
    }
}

__global__ void __launch_bounds__(256)
round_f16_k(__half* __restrict__ dst, const float* __restrict__ src)
{
    const size_t i = ((size_t)blockIdx.x * blockDim.x + threadIdx.x) * 4;
    const float4 v = *reinterpret_cast<const float4*>(src + i);
    __half2 lo = __floats2half2_rn(v.x, v.y);
    __half2 hi = __floats2half2_rn(v.z, v.w);
    uint2 o = make_uint2(*reinterpret_cast<uint32_t*>(&lo),
                         *reinterpret_cast<uint32_t*>(&hi));
    *reinterpret_cast<uint2*>(dst + i) = o;
}

// src [E][K][N] f32 -> dst [E][N][K] fp16. block (32,8), half2 stores.
__global__ void __launch_bounds__(256)
transpose_f16(__half* __restrict__ dst, const float* __restrict__ src,
              int K, int N)
{
    __shared__ float tile[32][33];
    const int tx = threadIdx.x, ty = threadIdx.y;
    const int tid = ty * 32 + tx;
    const int n0 = blockIdx.x * 32, k0 = blockIdx.y * 32, e = blockIdx.z;
    const float* s = src + (size_t)e * K * N;
    __half* d = dst + (size_t)e * N * K;
#pragma unroll
    for (int j = 0; j < 4; j++)
        tile[ty + 8 * j][tx] = s[(size_t)(k0 + ty + 8 * j) * N + n0 + tx];
    __syncthreads();
    // write: 256 threads -> 32 n-rows x 16 half2 (k pairs), 2 passes
    const int kp = (tid & 15) * 2;           // k pair base
#pragma unroll
    for (int j = 0; j < 2; j++) {
        const int nl = (tid >> 4) + j * 16;  // local n row
        __half2 v = __floats2half2_rn(tile[kp][nl], tile[kp + 1][nl]);
        *reinterpret_cast<uint32_t*>(d + (size_t)(n0 + nl) * K + k0 + kp) =
            *reinterpret_cast<uint32_t*>(&v);
    }
}

extern "C" void kernel_launch(void* const* d_in, const int* in_sizes, int n_in,
                              void* d_out, int out_size) {
    (void)in_sizes; (void)n_in; (void)out_size;
    const float* h  = (const float*)d_in[0];
    const float* w1 = (const float*)d_in[1];
    const float* w2 = (const float*)d_in[2];
    float* out = (float*)d_out;

    __half *act, *hh, *w1t, *w2t;
    cudaGetSymbolAddress((void**)&act, g_act);
    cudaGetSymbolAddress((void**)&hh,  g_hh);
    cudaGetSymbolAddress((void**)&w1t, g_w1t);
    cudaGetSymbolAddress((void**)&w2t, g_w2t);

    cudaFuncSetAttribute(gemm1_act,
                         cudaFuncAttributeMaxDynamicSharedMemorySize, SMEM_TOTAL);
    cudaFuncSetAttribute(gemm2,
                         cudaFuncAttributeMaxDynamicSharedMemorySize, SMEM_TOTAL);

    round_f16_k<<<(8192ull * 2048 / 4) / 256, 256>>>(hh, h);
    transpose_f16<<<dim3(4096 / 32, 2048 / 32, 8), dim3(32, 8)>>>(w1t, w1, 2048, 4096);
    transpose_f16<<<dim3(2048 / 32, 2048 / 32, 8), dim3(32, 8)>>>(w2t, w2, 2048, 2048);

    gemm1_act<<<dim3(32, 8, 8), 128, SMEM_TOTAL>>>(hh, w1t, act);
    gemm2<<<dim3(16, 8, 8), 128, SMEM_TOTAL>>>(act, w2t, out);
}

// round 10
// speedup vs baseline: 1.1633x; 1.0641x over previous
#include <cuda_runtime.h>
#include <cuda_fp16.h>
#include <cstdint>
#include <cstddef>

// ============================================================================
// MoE FFN, sm_103 baseline. fp16 mma.sync m16n8k16, BK=64, 3-stage cp.async.
// R10: B fragments via ldmatrix.x4.TRANS from natural [E][K][N] fp16 weights
//      -> transpose pre-passes replaced by pure streaming f32->f16 rounds.
//   PRE  : h, W1, W2 -> fp16 (same layout)
//   G1A  : act = fp16(up * relu(gate))   (fused epilogue)
//   GEMM2: out = act @ W2
// ============================================================================

#define KD 2048

__device__ __half g_act[8192ull * 2048ull];          //  33 MB
__device__ __half g_hh [8192ull * 2048ull];          //  33 MB
__device__ __half g_w1h[8ull * 2048ull * 4096ull];   // 134 MB W1 [E][K][4096]
__device__ __half g_w2h[8ull * 2048ull * 2048ull];   //  67 MB W2 [E][K][2048]

// A tile: 128 token-rows x 64 halves, pad to 144 B/row (as R9, proven).
static constexpr int STRIDE_H = 72;                  // halves
static constexpr int ROW_A    = STRIDE_H * 2;        // 144 B
static constexpr int TILE_A   = 128 * ROW_A;         // 18432
// B tile: 64 k-rows x 128 halves (256 B) + 16 pad = 272 B/row.
static constexpr int ROW_BB   = 272;
static constexpr int TILE_BB  = 64 * ROW_BB;         // 17408
static constexpr int STAGE_B  = TILE_A + TILE_BB;    // 35840
static constexpr int STAGES   = 3;
static constexpr int SMEM_TOTAL = STAGE_B * STAGES;  // 107520

__device__ __forceinline__ uint32_t smem_u32(const void* p) {
    uint32_t a;
    asm("{ .reg .u64 t; cvta.to.shared.u64 t, %1; cvt.u32.u64 %0, t; }"
        : "=r"(a) : "l"(p));
    return a;
}

#define CP16(d, s) asm volatile("cp.async.cg.shared.global [%0], [%1], 16;" \
                                :: "r"(d), "l"(s))
#define CP_COMMIT() asm volatile("cp.async.commit_group;" ::: "memory")
#define CP_WAITG(n) asm volatile("cp.async.wait_group %0;" :: "n"(n) : "memory")

#define LDSM_X4(r0, r1, r2, r3, a) asm volatile(                             \
    "ldmatrix.sync.aligned.m8n8.x4.shared.b16 {%0,%1,%2,%3}, [%4];"          \
    : "=r"(r0), "=r"(r1), "=r"(r2), "=r"(r3) : "r"(a))

#define LDSM_X4_T(r0, r1, r2, r3, a) asm volatile(                           \
    "ldmatrix.sync.aligned.m8n8.x4.trans.shared.b16 {%0,%1,%2,%3}, [%4];"    \
    : "=r"(r0), "=r"(r1), "=r"(r2), "=r"(r3) : "r"(a))

__device__ __forceinline__ void mma_f16(float c[4], const uint32_t a[4],
                                        const uint32_t b[2]) {
    asm volatile(
        "mma.sync.aligned.m16n8k16.row.col.f32.f16.f16.f32 "
        "{%0,%1,%2,%3}, {%4,%5,%6,%7}, {%8,%9}, {%0,%1,%2,%3};"
        : "+f"(c[0]), "+f"(c[1]), "+f"(c[2]), "+f"(c[3])
        : "r"(a[0]), "r"(a[1]), "r"(a[2]), "r"(a[3]), "r"(b[0]), "r"(b[1]));
}

// A: per-lane x4 offset (unchanged layout): tiles {m-lo,k-lo},{m-hi,k-lo},
// {m-lo,k-hi},{m-hi,k-hi}
__device__ __forceinline__ uint32_t ldsm_offA(int lane) {
    const int r8 = lane & 7;
    return (uint32_t)(((((lane >> 3) & 1) * 8 + r8) * STRIDE_H
                       + (lane >> 4) * 8) * 2);
}
// B (trans, [k][n] storage): tiles {k-lo,n-lo},{k-hi,n-lo},{k-lo,n-hi},
// {k-hi,n-hi}; address = k-row start + n byte offset
__device__ __forceinline__ uint32_t ldsm_offB_T(int lane) {
    const int t = lane >> 3, r8 = lane & 7;
    return (uint32_t)(((t & 1) * 8 + r8) * ROW_BB + (t >> 1) * 8 * 2);
}

// one ks step, warp tile 64x64. A: +32 B per ks; B: +16 k-rows per ks.
#define KS_STEP64(ks, st, abase, bbase, acc) do {                            \
    const uint32_t _koA = (uint32_t)((ks) * 32);                             \
    const uint32_t _koB = (uint32_t)((ks) * 16 * ROW_BB);                    \
    uint32_t _af[4][4], _bf[8][2];                                           \
    _Pragma("unroll")                                                        \
    for (int _mi = 0; _mi < 4; _mi++)                                        \
        LDSM_X4(_af[_mi][0], _af[_mi][1], _af[_mi][2], _af[_mi][3],          \
                (st) + (abase) + _koA + (uint32_t)(_mi * 16 * ROW_A));       \
    _Pragma("unroll")                                                        \
    for (int _b = 0; _b < 4; _b++)                                           \
        LDSM_X4_T(_bf[2 * _b][0], _bf[2 * _b][1],                            \
                  _bf[2 * _b + 1][0], _bf[2 * _b + 1][1],                    \
                  (st) + (bbase) + _koB + (uint32_t)(_b * 32));              \
    _Pragma("unroll")                                                        \
    for (int _mi = 0; _mi < 4; _mi++)                                        \
        _Pragma("unroll")                                                    \
        for (int _ni = 0; _ni < 8; _ni++)                                    \
            mma_f16(acc[_mi][_ni], _af[_mi], _bf[_ni]);                      \
} while (0)

// ---------------------------------------------------------------------------
// GEMM1 fused with activation. CTA: 128 tokens x 64 act cols.
// B tile n 0-63 = gate cols (W1 n = nt*64+..), n 64-127 = up cols (+2048).
// ---------------------------------------------------------------------------
__global__ void __launch_bounds__(128, 2)
gemm1_act(const __half* __restrict__ X, const __half* __restrict__ W1h,
          __half* __restrict__ Act)
{
    extern __shared__ __align__(16) char smem[];
    const int tid = threadIdx.x;
    const int wid = tid >> 5, lane = tid & 31;
    const int g = lane >> 2, tg = lane & 3;
    const int wm = wid & 1, wn = wid >> 1;
    const int nt = blockIdx.x, tt = blockIdx.y, e = blockIdx.z;

    const __half* Ag = X + (size_t)(e * 1024 + tt * 128) * KD;
    const uint32_t sbase = smem_u32(smem);

    // A cp.async: 16 rows x 8 chunks per pass, 8 passes
    const int cr = tid >> 3, cc = tid & 7;
    const uint32_t cdstA = (uint32_t)(cr * ROW_A + cc * 16);
    // B cp.async: 8 k-rows x 16 chunks per pass, 8 passes
    const int cr2 = tid >> 4, cc2 = tid & 15;
    const uint32_t cdstB = (uint32_t)(cr2 * ROW_BB + cc2 * 16);
    // per-thread W1 column base: gate (cc2<8) or up (cc2>=8)
    const int ncol = nt * 64 + (cc2 & 7) * 8 + ((cc2 >= 8) ? 2048 : 0);
    const __half* Bg = W1h + (size_t)e * KD * 4096 + ncol;

    auto load_stage = [&](int buf, int kt) {
        const uint32_t sa = sbase + (uint32_t)buf * STAGE_B;
        const uint32_t sb = sa + TILE_A;
        const __half* a = Ag + kt * 64;
#pragma unroll
        for (int j = 0; j < 8; j++)
            CP16(sa + cdstA + (uint32_t)(j * 16 * ROW_A),
                 a + (size_t)(cr + j * 16) * KD + cc * 8);
        const __half* b = Bg + (size_t)(kt * 64 + cr2) * 4096;
#pragma unroll
        for (int j = 0; j < 8; j++)
            CP16(sb + cdstB + (uint32_t)(j * 8 * ROW_BB),
                 b + (size_t)(j * 8) * 4096);
        CP_COMMIT();
    };

    const uint32_t abase = (uint32_t)(wm * 64 * ROW_A) + ldsm_offA(lane);
    const uint32_t bbase = (uint32_t)(wn * 128) + ldsm_offB_T(lane) + TILE_A;

    float acc[4][8][4];
#pragma unroll
    for (int mi = 0; mi < 4; mi++)
#pragma unroll
        for (int ni = 0; ni < 8; ni++)
#pragma unroll
            for (int q = 0; q < 4; q++) acc[mi][ni][q] = 0.f;

    load_stage(0, 0);
    load_stage(1, 1);

    constexpr int NKT = KD / 64;   // 32
    for (int kt = 0; kt < NKT; kt++) {
        if (kt == NKT - 1) { CP_WAITG(0); } else { CP_WAITG(1); }
        __syncthreads();
        if (kt + 2 < NKT) load_stage((kt + 2) % STAGES, kt + 2);

        const uint32_t st = sbase + (uint32_t)((kt % STAGES) * STAGE_B);
#pragma unroll
        for (int ks = 0; ks < 4; ks++)
            KS_STEP64(ks, st, abase, bbase, acc);
    }

    // ---- fused act epilogue (stride 66 f32, 8B-aligned float2) ----------
    __syncthreads();
    float* ex = reinterpret_cast<float*>(smem) + wm * (64 * 66);
    if (wn == 1) {                         // up warps publish
#pragma unroll
        for (int mi = 0; mi < 4; mi++) {
            const int r0 = mi * 16 + g;
#pragma unroll
            for (int ni = 0; ni < 8; ni++) {
                const int cb = ni * 8 + tg * 2;
                *reinterpret_cast<float2*>(ex + r0 * 66 + cb) =
                    make_float2(acc[mi][ni][0], acc[mi][ni][1]);
                *reinterpret_cast<float2*>(ex + (r0 + 8) * 66 + cb) =
                    make_float2(acc[mi][ni][2], acc[mi][ni][3]);
            }
        }
    }
    __syncthreads();
    if (wn == 0) {                         // gate warps combine + store
        __half* Og = Act + (size_t)(e * 1024 + tt * 128 + wm * 64) * 2048
                   + nt * 64;
#pragma unroll
        for (int mi = 0; mi < 4; mi++) {
            const int r0 = mi * 16 + g;
#pragma unroll
            for (int ni = 0; ni < 8; ni++) {
                const int cb = ni * 8 + tg * 2;
                const float2 ulo = *reinterpret_cast<float2*>(ex + r0 * 66 + cb);
                const float2 uhi =
                    *reinterpret_cast<float2*>(ex + (r0 + 8) * 66 + cb);
                __half2 lo = __floats2half2_rn(
                    ulo.x * fmaxf(acc[mi][ni][0], 0.f),
                    ulo.y * fmaxf(acc[mi][ni][1], 0.f));
                __half2 hi = __floats2half2_rn(
                    uhi.x * fmaxf(acc[mi][ni][2], 0.f),
                    uhi.y * fmaxf(acc[mi][ni][3], 0.f));
                *reinterpret_cast<uint32_t*>(Og + (size_t)r0 * 2048 + cb) =
                    *reinterpret_cast<uint32_t*>(&lo);
                *reinterpret_cast<uint32_t*>(Og + (size_t)(r0 + 8) * 2048 + cb) =
                    *reinterpret_cast<uint32_t*>(&hi);
            }
        }
    }
}

// ---------------------------------------------------------------------------
// GEMM2: 128x128 CTA tile, B from W2 [E][K][2048] via trans ldmatrix.
// ---------------------------------------------------------------------------
__global__ void __launch_bounds__(128, 2)
gemm2(const __half* __restrict__ X, const __half* __restrict__ W2h,
      float* __restrict__ C)
{
    extern __shared__ __align__(16) char smem[];
    const int tid = threadIdx.x;
    const int wid = tid >> 5, lane = tid & 31;
    const int g = lane >> 2, tg = lane & 3;
    const int wm = wid & 1, wn = wid >> 1;
    const int nt = blockIdx.x, tt = blockIdx.y, e = blockIdx.z;
    constexpr int WN = 2048;

    const __half* Ag = X + (size_t)(e * 1024 + tt * 128) * KD;
    const uint32_t sbase = smem_u32(smem);

    const int cr = tid >> 3, cc = tid & 7;
    const uint32_t cdstA = (uint32_t)(cr * ROW_A + cc * 16);
    const int cr2 = tid >> 4, cc2 = tid & 15;
    const uint32_t cdstB = (uint32_t)(cr2 * ROW_BB + cc2 * 16);
    const __half* Bg = W2h + (size_t)e * KD * WN + nt * 128 + cc2 * 8;

    auto load_stage = [&](int buf, int kt) {
        const uint32_t sa = sbase + (uint32_t)buf * STAGE_B;
        const uint32_t sb = sa + TILE_A;
        const __half* a = Ag + kt * 64;
#pragma unroll
        for (int j = 0; j < 8; j++)
            CP16(sa + cdstA + (uint32_t)(j * 16 * ROW_A),
                 a + (size_t)(cr + j * 16) * KD + cc * 8);
        const __half* b = Bg + (size_t)(kt * 64 + cr2) * WN;
#pragma unroll
        for (int j = 0; j < 8; j++)
            CP16(sb + cdstB + (uint32_t)(j * 8 * ROW_BB),
                 b + (size_t)(j * 8) * WN);
        CP_COMMIT();
    };

    const uint32_t abase = (uint32_t)(wm * 64 * ROW_A) + ldsm_offA(lane);
    const uint32_t bbase = (uint32_t)(wn * 128) + ldsm_offB_T(lane) + TILE_A;

    float acc[4][8][4];
#pragma unroll
    for (int mi = 0; mi < 4; mi++)
#pragma unroll
        for (int ni = 0; ni < 8; ni++)
#pragma unroll
            for (int q = 0; q < 4; q++) acc[mi][ni][q] = 0.f;

    load_stage(0, 0);
    load_stage(1, 1);

    constexpr int NKT = KD / 64;   // 32
    for (int kt = 0; kt < NKT; kt++) {
        if (kt == NKT - 1) { CP_WAITG(0); } else { CP_WAITG(1); }
        __syncthreads();
        if (kt + 2 < NKT) load_stage((kt + 2) % STAGES, kt + 2);

        const uint32_t st = sbase + (uint32_t)((kt % STAGES) * STAGE_B);
#pragma unroll
        for (int ks = 0; ks < 4; ks++)
            KS_STEP64(ks, st, abase, bbase, acc);
    }

    float* Cg = C + (size_t)(e * 1024 + tt * 128) * WN + nt * 128;
#pragma unroll
    for (int mi = 0; mi < 4; mi++) {
        const int r0 = wm * 64 + mi * 16 + g;
#pragma unroll
        for (int ni = 0; ni < 8; ni++) {
            const int cb = wn * 64 + ni * 8 + tg * 2;
            float2 lo = make_float2(acc[mi][ni][0], acc[mi][ni][1]);
            float2 hi = make_float2(acc[mi][ni][2], acc[mi][ni][3]);
            *reinterpret_cast<float2*>(Cg + (size_t)r0 * WN + cb) = lo;
            *reinterpret_cast<float2*>(Cg + (size_t)(r0 + 8) * WN + cb) = hi;
        }
    }
}

__global__ void __launch_bounds__(256)
round_f16_k(__half* __restrict__ dst, const float* __restrict__ src)
{
    const size_t i = ((size_t)blockIdx.x * blockDim.x + threadIdx.x) * 4;
    const float4 v = *reinterpret_cast<const float4*>(src + i);
    __half2 lo = __floats2half2_rn(v.x, v.y);
    __half2 hi = __floats2half2_rn(v.z, v.w);
    uint2 o = make_uint2(*reinterpret_cast<uint32_t*>(&lo),
                         *reinterpret_cast<uint32_t*>(&hi));
    *reinterpret_cast<uint2*>(dst + i) = o;
}

extern "C" void kernel_launch(void* const* d_in, const int* in_sizes, int n_in,
                              void* d_out, int out_size) {
    (void)in_sizes; (void)n_in; (void)out_size;
    const float* h  = (const float*)d_in[0];
    const float* w1 = (const float*)d_in[1];
    const float* w2 = (const float*)d_in[2];
    float* out = (float*)d_out;

    __half *act, *hh, *w1h, *w2h;
    cudaGetSymbolAddress((void**)&act, g_act);
    cudaGetSymbolAddress((void**)&hh,  g_hh);
    cudaGetSymbolAddress((void**)&w1h, g_w1h);
    cudaGetSymbolAddress((void**)&w2h, g_w2h);

    cudaFuncSetAttribute(gemm1_act,
                         cudaFuncAttributeMaxDynamicSharedMemorySize, SMEM_TOTAL);
    cudaFuncSetAttribute(gemm2,
                         cudaFuncAttributeMaxDynamicSharedMemorySize, SMEM_TOTAL);

    round_f16_k<<<(8192ull * 2048 / 4) / 256, 256>>>(hh, h);
    round_f16_k<<<(8ull * 2048 * 4096 / 4) / 256, 256>>>(w1h, w1);
    round_f16_k<<<(8ull * 2048 * 2048 / 4) / 256, 256>>>(w2h, w2);

    gemm1_act<<<dim3(32, 8, 8), 128, SMEM_TOTAL>>>(hh, w1h, act);
    gemm2<<<dim3(16, 8, 8), 128, SMEM_TOTAL>>>(act, w2h, out);
}

// round 11
// speedup vs baseline: 1.1677x; 1.0037x over previous
#include <cuda_runtime.h>
#include <cuda_fp16.h>
#include <cstdint>
#include <cstddef>

// ============================================================================
// MoE FFN, sm_103 baseline. fp16 mma.sync m16n8k16, BK=64, 3-stage cp.async,
// trans-ldmatrix B from natural [E][K][N] weights.
// R11: 256-thread CTA, warp tile 32x64 (acc=64 regs), 2 CTAs/SM -> 16 warps
//      = 4/SMSP for latency hiding.
//   PRE  : h, W1, W2 -> fp16 (same layout)
//   G1A  : act = fp16(up * relu(gate))   (fused epilogue)
//   GEMM2: out = act @ W2
// ============================================================================

#define KD 2048

__device__ __half g_act[8192ull * 2048ull];          //  33 MB
__device__ __half g_hh [8192ull * 2048ull];          //  33 MB
__device__ __half g_w1h[8ull * 2048ull * 4096ull];   // 134 MB W1 [E][K][4096]
__device__ __half g_w2h[8ull * 2048ull * 2048ull];   //  67 MB W2 [E][K][2048]

static constexpr int STRIDE_H = 72;                  // halves
static constexpr int ROW_A    = STRIDE_H * 2;        // 144 B
static constexpr int TILE_A   = 128 * ROW_A;         // 18432
static constexpr int ROW_BB   = 272;                 // 128 halves + 16B pad
static constexpr int TILE_BB  = 64 * ROW_BB;         // 17408
static constexpr int STAGE_B  = TILE_A + TILE_BB;    // 35840
static constexpr int STAGES   = 3;
static constexpr int SMEM_TOTAL = STAGE_B * STAGES;  // 107520

__device__ __forceinline__ uint32_t smem_u32(const void* p) {
    uint32_t a;
    asm("{ .reg .u64 t; cvta.to.shared.u64 t, %1; cvt.u32.u64 %0, t; }"
        : "=r"(a) : "l"(p));
    return a;
}

#define CP16(d, s) asm volatile("cp.async.cg.shared.global [%0], [%1], 16;" \
                                :: "r"(d), "l"(s))
#define CP_COMMIT() asm volatile("cp.async.commit_group;" ::: "memory")
#define CP_WAITG(n) asm volatile("cp.async.wait_group %0;" :: "n"(n) : "memory")

#define LDSM_X4(r0, r1, r2, r3, a) asm volatile(                             \
    "ldmatrix.sync.aligned.m8n8.x4.shared.b16 {%0,%1,%2,%3}, [%4];"          \
    : "=r"(r0), "=r"(r1), "=r"(r2), "=r"(r3) : "r"(a))

#define LDSM_X4_T(r0, r1, r2, r3, a) asm volatile(                           \
    "ldmatrix.sync.aligned.m8n8.x4.trans.shared.b16 {%0,%1,%2,%3}, [%4];"    \
    : "=r"(r0), "=r"(r1), "=r"(r2), "=r"(r3) : "r"(a))

__device__ __forceinline__ void mma_f16(float c[4], const uint32_t a[4],
                                        const uint32_t b[2]) {
    asm volatile(
        "mma.sync.aligned.m16n8k16.row.col.f32.f16.f16.f32 "
        "{%0,%1,%2,%3}, {%4,%5,%6,%7}, {%8,%9}, {%0,%1,%2,%3};"
        : "+f"(c[0]), "+f"(c[1]), "+f"(c[2]), "+f"(c[3])
        : "r"(a[0]), "r"(a[1]), "r"(a[2]), "r"(a[3]), "r"(b[0]), "r"(b[1]));
}

// A x4 (16 rows x 16 halves): tiles {m-lo,k-lo},{m-hi,k-lo},{m-lo,k-hi},{m-hi,k-hi}
__device__ __forceinline__ uint32_t ldsm_offA(int lane) {
    const int r8 = lane & 7;
    return (uint32_t)(((((lane >> 3) & 1) * 8 + r8) * STRIDE_H
                       + (lane >> 4) * 8) * 2);
}
// B trans x4 ([k][n] storage): {k-lo,n-lo},{k-hi,n-lo},{k-lo,n-hi},{k-hi,n-hi}
__device__ __forceinline__ uint32_t ldsm_offB_T(int lane) {
    const int t = lane >> 3, r8 = lane & 7;
    return (uint32_t)(((t & 1) * 8 + r8) * ROW_BB + (t >> 1) * 8 * 2);
}

// one ks step, warp tile 32x64: 2 A-LDSM + 4 B-LDSM(T) + 16 MMA
#define KS_STEP32(ks, st, abase, bbase, acc) do {                            \
    const uint32_t _koA = (uint32_t)((ks) * 32);                             \
    const uint32_t _koB = (uint32_t)((ks) * 16 * ROW_BB);                    \
    uint32_t _af[2][4], _bf[8][2];                                           \
    _Pragma("unroll")                                                        \
    for (int _mi = 0; _mi < 2; _mi++)                                        \
        LDSM_X4(_af[_mi][0], _af[_mi][1], _af[_mi][2], _af[_mi][3],          \
                (st) + (abase) + _koA + (uint32_t)(_mi * 16 * ROW_A));       \
    _Pragma("unroll")                                                        \
    for (int _b = 0; _b < 4; _b++)                                           \
        LDSM_X4_T(_bf[2 * _b][0], _bf[2 * _b][1],                            \
                  _bf[2 * _b + 1][0], _bf[2 * _b + 1][1],                    \
                  (st) + (bbase) + _koB + (uint32_t)(_b * 32));              \
    _Pragma("unroll")                                                        \
    for (int _mi = 0; _mi < 2; _mi++)                                        \
        _Pragma("unroll")                                                    \
        for (int _ni = 0; _ni < 8; _ni++)                                    \
            mma_f16(acc[_mi][_ni], _af[_mi], _bf[_ni]);                      \
} while (0)

// ---------------------------------------------------------------------------
// GEMM1 fused with activation. CTA 128 tokens x 64 act cols; 8 warps 4Mx2N.
// B tile n 0-63 = gate cols, n 64-127 = up cols (+2048 in W1).
// ---------------------------------------------------------------------------
__global__ void __launch_bounds__(256, 2)
gemm1_act(const __half* __restrict__ X, const __half* __restrict__ W1h,
          __half* __restrict__ Act)
{
    extern __shared__ __align__(16) char smem[];
    const int tid = threadIdx.x;
    const int wid = tid >> 5, lane = tid & 31;
    const int g = lane >> 2, tg = lane & 3;
    const int wm = wid & 3, wn = wid >> 2;
    const int nt = blockIdx.x, tt = blockIdx.y, e = blockIdx.z;

    const __half* Ag = X + (size_t)(e * 1024 + tt * 128) * KD;
    const uint32_t sbase = smem_u32(smem);

    // cp.async: A 128 rows x 8 chunks (4/thr); B 64 k-rows x 16 chunks (4/thr)
    const int cr = tid >> 3, cc = tid & 7;          // A: 32 rows/pass
    const uint32_t cdstA = (uint32_t)(cr * ROW_A + cc * 16);
    const int cr2 = tid >> 4, cc2 = tid & 15;       // B: 16 k-rows/pass
    const uint32_t cdstB = (uint32_t)(cr2 * ROW_BB + cc2 * 16);
    const int ncol = nt * 64 + (cc2 & 7) * 8 + ((cc2 >= 8) ? 2048 : 0);
    const __half* Bg = W1h + (size_t)e * KD * 4096 + ncol;

    auto load_stage = [&](int buf, int kt) {
        const uint32_t sa = sbase + (uint32_t)buf * STAGE_B;
        const uint32_t sb = sa + TILE_A;
        const __half* a = Ag + kt * 64;
#pragma unroll
        for (int j = 0; j < 4; j++)
            CP16(sa + cdstA + (uint32_t)(j * 32 * ROW_A),
                 a + (size_t)(cr + j * 32) * KD + cc * 8);
        const __half* b = Bg + (size_t)(kt * 64 + cr2) * 4096;
#pragma unroll
        for (int j = 0; j < 4; j++)
            CP16(sb + cdstB + (uint32_t)(j * 16 * ROW_BB),
                 b + (size_t)(j * 16) * 4096);
        CP_COMMIT();
    };

    const uint32_t abase = (uint32_t)(wm * 32 * ROW_A) + ldsm_offA(lane);
    const uint32_t bbase = (uint32_t)(wn * 128) + ldsm_offB_T(lane) + TILE_A;

    float acc[2][8][4];
#pragma unroll
    for (int mi = 0; mi < 2; mi++)
#pragma unroll
        for (int ni = 0; ni < 8; ni++)
#pragma unroll
            for (int q = 0; q < 4; q++) acc[mi][ni][q] = 0.f;

    load_stage(0, 0);
    load_stage(1, 1);

    constexpr int NKT = KD / 64;   // 32
    for (int kt = 0; kt < NKT; kt++) {
        if (kt == NKT - 1) { CP_WAITG(0); } else { CP_WAITG(1); }
        __syncthreads();
        if (kt + 2 < NKT) load_stage((kt + 2) % STAGES, kt + 2);

        const uint32_t st = sbase + (uint32_t)((kt % STAGES) * STAGE_B);
#pragma unroll
        for (int ks = 0; ks < 4; ks++)
            KS_STEP32(ks, st, abase, bbase, acc);
    }

    // ---- fused act epilogue: ex[wm] = 32 rows x 66 f32 ------------------
    __syncthreads();
    float* ex = reinterpret_cast<float*>(smem) + wm * (32 * 66);
    if (wn == 1) {                          // up warps publish
#pragma unroll
        for (int mi = 0; mi < 2; mi++) {
            const int r0 = mi * 16 + g;
#pragma unroll
            for (int ni = 0; ni < 8; ni++) {
                const int cb = ni * 8 + tg * 2;
                *reinterpret_cast<float2*>(ex + r0 * 66 + cb) =
                    make_float2(acc[mi][ni][0], acc[mi][ni][1]);
                *reinterpret_cast<float2*>(ex + (r0 + 8) * 66 + cb) =
                    make_float2(acc[mi][ni][2], acc[mi][ni][3]);
            }
        }
    }
    __syncthreads();
    if (wn == 0) {                          // gate warps combine + store
        __half* Og = Act + (size_t)(e * 1024 + tt * 128 + wm * 32) * 2048
                   + nt * 64;
#pragma unroll
        for (int mi = 0; mi < 2; mi++) {
            const int r0 = mi * 16 + g;
#pragma unroll
            for (int ni = 0; ni < 8; ni++) {
                const int cb = ni * 8 + tg * 2;
                const float2 ulo = *reinterpret_cast<float2*>(ex + r0 * 66 + cb);
                const float2 uhi =
                    *reinterpret_cast<float2*>(ex + (r0 + 8) * 66 + cb);
                __half2 lo = __floats2half2_rn(
                    ulo.x * fmaxf(acc[mi][ni][0], 0.f),
                    ulo.y * fmaxf(acc[mi][ni][1], 0.f));
                __half2 hi = __floats2half2_rn(
                    uhi.x * fmaxf(acc[mi][ni][2], 0.f),
                    uhi.y * fmaxf(acc[mi][ni][3], 0.f));
                *reinterpret_cast<uint32_t*>(Og + (size_t)r0 * 2048 + cb) =
                    *reinterpret_cast<uint32_t*>(&lo);
                *reinterpret_cast<uint32_t*>(Og + (size_t)(r0 + 8) * 2048 + cb) =
                    *reinterpret_cast<uint32_t*>(&hi);
            }
        }
    }
}

// ---------------------------------------------------------------------------
// GEMM2: 128x128 CTA tile, 8 warps 4Mx2N, fp32 out.
// ---------------------------------------------------------------------------
__global__ void __launch_bounds__(256, 2)
gemm2(const __half* __restrict__ X, const __half* __restrict__ W2h,
      float* __restrict__ C)
{
    extern __shared__ __align__(16) char smem[];
    const int tid = threadIdx.x;
    const int wid = tid >> 5, lane = tid & 31;
    const int g = lane >> 2, tg = lane & 3;
    const int wm = wid & 3, wn = wid >> 2;
    const int nt = blockIdx.x, tt = blockIdx.y, e = blockIdx.z;
    constexpr int WN = 2048;

    const __half* Ag = X + (size_t)(e * 1024 + tt * 128) * KD;
    const uint32_t sbase = smem_u32(smem);

    const int cr = tid >> 3, cc = tid & 7;
    const uint32_t cdstA = (uint32_t)(cr * ROW_A + cc * 16);
    const int cr2 = tid >> 4, cc2 = tid & 15;
    const uint32_t cdstB = (uint32_t)(cr2 * ROW_BB + cc2 * 16);
    const __half* Bg = W2h + (size_t)e * KD * WN + nt * 128 + cc2 * 8;

    auto load_stage = [&](int buf, int kt) {
        const uint32_t sa = sbase + (uint32_t)buf * STAGE_B;
        const uint32_t sb = sa + TILE_A;
        const __half* a = Ag + kt * 64;
#pragma unroll
        for (int j = 0; j < 4; j++)
            CP16(sa + cdstA + (uint32_t)(j * 32 * ROW_A),
                 a + (size_t)(cr + j * 32) * KD + cc * 8);
        const __half* b = Bg + (size_t)(kt * 64 + cr2) * WN;
#pragma unroll
        for (int j = 0; j < 4; j++)
            CP16(sb + cdstB + (uint32_t)(j * 16 * ROW_BB),
                 b + (size_t)(j * 16) * WN);
        CP_COMMIT();
    };

    const uint32_t abase = (uint32_t)(wm * 32 * ROW_A) + ldsm_offA(lane);
    const uint32_t bbase = (uint32_t)(wn * 128) + ldsm_offB_T(lane) + TILE_A;

    float acc[2][8][4];
#pragma unroll
    for (int mi = 0; mi < 2; mi++)
#pragma unroll
        for (int ni = 0; ni < 8; ni++)
#pragma unroll
            for (int q = 0; q < 4; q++) acc[mi][ni][q] = 0.f;

    load_stage(0, 0);
    load_stage(1, 1);

    constexpr int NKT = KD / 64;   // 32
    for (int kt = 0; kt < NKT; kt++) {
        if (kt == NKT - 1) { CP_WAITG(0); } else { CP_WAITG(1); }
        __syncthreads();
        if (kt + 2 < NKT) load_stage((kt + 2) % STAGES, kt + 2);

        const uint32_t st = sbase + (uint32_t)((kt % STAGES) * STAGE_B);
#pragma unroll
        for (int ks = 0; ks < 4; ks++)
            KS_STEP32(ks, st, abase, bbase, acc);
    }

    float* Cg = C + (size_t)(e * 1024 + tt * 128) * WN + nt * 128;
#pragma unroll
    for (int mi = 0; mi < 2; mi++) {
        const int r0 = wm * 32 + mi * 16 + g;
#pragma unroll
        for (int ni = 0; ni < 8; ni++) {
            const int cb = wn * 64 + ni * 8 + tg * 2;
            float2 lo = make_float2(acc[mi][ni][0], acc[mi][ni][1]);
            float2 hi = make_float2(acc[mi][ni][2], acc[mi][ni][3]);
            *reinterpret_cast<float2*>(Cg + (size_t)r0 * WN + cb) = lo;
            *reinterpret_cast<float2*>(Cg + (size_t)(r0 + 8) * WN + cb) = hi;
        }
    }
}

__global__ void __launch_bounds__(256)
round_f16_k(__half* __restrict__ dst, const float* __restrict__ src)
{
    const size_t i = ((size_t)blockIdx.x * blockDim.x + threadIdx.x) * 4;
    const float4 v = *reinterpret_cast<const float4*>(src + i);
    __half2 lo = __floats2half2_rn(v.x, v.y);
    __half2 hi = __floats2half2_rn(v.z, v.w);
    uint2 o = make_uint2(*reinterpret_cast<uint32_t*>(&lo),
                         *reinterpret_cast<uint32_t*>(&hi));
    *reinterpret_cast<uint2*>(dst + i) = o;
}

extern "C" void kernel_launch(void* const* d_in, const int* in_sizes, int n_in,
                              void* d_out, int out_size) {
    (void)in_sizes; (void)n_in; (void)out_size;
    const float* h  = (const float*)d_in[0];
    const float* w1 = (const float*)d_in[1];
    const float* w2 = (const float*)d_in[2];
    float* out = (float*)d_out;

    __half *act, *hh, *w1h, *w2h;
    cudaGetSymbolAddress((void**)&act, g_act);
    cudaGetSymbolAddress((void**)&hh,  g_hh);
    cudaGetSymbolAddress((void**)&w1h, g_w1h);
    cudaGetSymbolAddress((void**)&w2h, g_w2h);

    cudaFuncSetAttribute(gemm1_act,
                         cudaFuncAttributeMaxDynamicSharedMemorySize, SMEM_TOTAL);
    cudaFuncSetAttribute(gemm2,
                         cudaFuncAttributeMaxDynamicSharedMemorySize, SMEM_TOTAL);

    round_f16_k<<<(8192ull * 2048 / 4) / 256, 256>>>(hh, h);
    round_f16_k<<<(8ull * 2048 * 4096 / 4) / 256, 256>>>(w1h, w1);
    round_f16_k<<<(8ull * 2048 * 2048 / 4) / 256, 256>>>(w2h, w2);

    gemm1_act<<<dim3(32, 8, 8), 256, SMEM_TOTAL>>>(hh, w1h, act);
    gemm2<<<dim3(16, 8, 8), 256, SMEM_TOTAL>>>(act, w2h, out);
}

// round 12
// speedup vs baseline: 1.2190x; 1.0440x over previous
#include <cuda_runtime.h>
#include <cuda_fp16.h>
#include <cstdint>
#include <cstddef>

// ============================================================================
// MoE FFN, sm_103 baseline. fp16 mma.sync m16n8k16, BK=64, trans-ldmatrix B.
// R12: barrier-ahead pipeline — top-of-kt waits ALL in-flight cp.async
//      (stages kt and kt+1 visible), loads issued after the sync, and ks0
//      fragments of stage kt+1 prefetched across the barrier at the seam.
//      128-thr CTA, warp 64x64, 2 CTAs/SM, rotating fragment buffers.
//   PRE  : h, W1, W2 -> fp16 (same layout)
//   G1A  : act = fp16(up * relu(gate))   (fused epilogue)
//   GEMM2: out = act @ W2
// ============================================================================

#define KD 2048

__device__ __half g_act[8192ull * 2048ull];          //  33 MB
__device__ __half g_hh [8192ull * 2048ull];          //  33 MB
__device__ __half g_w1h[8ull * 2048ull * 4096ull];   // 134 MB W1 [E][K][4096]
__device__ __half g_w2h[8ull * 2048ull * 2048ull];   //  67 MB W2 [E][K][2048]

static constexpr int STRIDE_H = 72;                  // halves
static constexpr int ROW_A    = STRIDE_H * 2;        // 144 B
static constexpr int TILE_A   = 128 * ROW_A;         // 18432
static constexpr int ROW_BB   = 272;                 // 128 halves + 16B pad
static constexpr int TILE_BB  = 64 * ROW_BB;         // 17408
static constexpr int STAGE_B  = TILE_A + TILE_BB;    // 35840
static constexpr int STAGES   = 3;
static constexpr int SMEM_TOTAL = STAGE_B * STAGES;  // 107520

__device__ __forceinline__ uint32_t smem_u32(const void* p) {
    uint32_t a;
    asm("{ .reg .u64 t; cvta.to.shared.u64 t, %1; cvt.u32.u64 %0, t; }"
        : "=r"(a) : "l"(p));
    return a;
}

#define CP16(d, s) asm volatile("cp.async.cg.shared.global [%0], [%1], 16;" \
                                :: "r"(d), "l"(s))
#define CP_COMMIT() asm volatile("cp.async.commit_group;" ::: "memory")
#define CP_WAITG(n) asm volatile("cp.async.wait_group %0;" :: "n"(n) : "memory")

#define LDSM_X4(r0, r1, r2, r3, a) asm volatile(                             \
    "ldmatrix.sync.aligned.m8n8.x4.shared.b16 {%0,%1,%2,%3}, [%4];"          \
    : "=r"(r0), "=r"(r1), "=r"(r2), "=r"(r3) : "r"(a))

#define LDSM_X4_T(r0, r1, r2, r3, a) asm volatile(                           \
    "ldmatrix.sync.aligned.m8n8.x4.trans.shared.b16 {%0,%1,%2,%3}, [%4];"    \
    : "=r"(r0), "=r"(r1), "=r"(r2), "=r"(r3) : "r"(a))

__device__ __forceinline__ void mma_f16(float c[4], const uint32_t a[4],
                                        const uint32_t b[2]) {
    asm volatile(
        "mma.sync.aligned.m16n8k16.row.col.f32.f16.f16.f32 "
        "{%0,%1,%2,%3}, {%4,%5,%6,%7}, {%8,%9}, {%0,%1,%2,%3};"
        : "+f"(c[0]), "+f"(c[1]), "+f"(c[2]), "+f"(c[3])
        : "r"(a[0]), "r"(a[1]), "r"(a[2]), "r"(a[3]), "r"(b[0]), "r"(b[1]));
}

// A x4 (16 rows x 16 halves): {m-lo,k-lo},{m-hi,k-lo},{m-lo,k-hi},{m-hi,k-hi}
__device__ __forceinline__ uint32_t ldsm_offA(int lane) {
    const int r8 = lane & 7;
    return (uint32_t)(((((lane >> 3) & 1) * 8 + r8) * STRIDE_H
                       + (lane >> 4) * 8) * 2);
}
// B trans x4 ([k][n] storage): {k-lo,n-lo},{k-hi,n-lo},{k-lo,n-hi},{k-hi,n-hi}
__device__ __forceinline__ uint32_t ldsm_offB_T(int lane) {
    const int t = lane >> 3, r8 = lane & 7;
    return (uint32_t)(((t & 1) * 8 + r8) * ROW_BB + (t >> 1) * 8 * 2);
}

// load fragments for (stage st, k-slice ks) into rotating buffer pb
#define LDFRAG(pb, ks, st) do {                                              \
    const uint32_t _koA = (uint32_t)((ks) * 32);                             \
    const uint32_t _koB = (uint32_t)((ks) * 16 * ROW_BB);                    \
    _Pragma("unroll")                                                        \
    for (int _mi = 0; _mi < 4; _mi++)                                        \
        LDSM_X4(af[pb][_mi][0], af[pb][_mi][1], af[pb][_mi][2],              \
                af[pb][_mi][3],                                              \
                (st) + abase + _koA + (uint32_t)(_mi * 16 * ROW_A));         \
    _Pragma("unroll")                                                        \
    for (int _b = 0; _b < 4; _b++)                                           \
        LDSM_X4_T(bf[pb][2 * _b][0], bf[pb][2 * _b][1],                      \
                  bf[pb][2 * _b + 1][0], bf[pb][2 * _b + 1][1],              \
                  (st) + bbase + _koB + (uint32_t)(_b * 32));                \
} while (0)

#define MMA_STEP(pb) do {                                                    \
    _Pragma("unroll")                                                        \
    for (int _mi = 0; _mi < 4; _mi++)                                        \
        _Pragma("unroll")                                                    \
        for (int _ni = 0; _ni < 8; _ni++)                                    \
            mma_f16(acc[_mi][_ni], af[pb][_mi], bf[pb][_ni]);                \
} while (0)

// barrier-ahead mainloop (shared by both GEMMs); assumes load_stage lambda,
// abase/bbase, acc/af/bf in scope.
#define MAINLOOP()                                                           \
    load_stage(0, 0);                                                        \
    load_stage(1, 1);                                                        \
    for (int kt = 0; kt < NKT; kt++) {                                       \
        CP_WAITG(0);                                                         \
        __syncthreads();                                                     \
        if (kt + 2 < NKT) load_stage((kt + 2) % STAGES, kt + 2);             \
        const uint32_t st = sbase + (uint32_t)((kt % STAGES) * STAGE_B);     \
        const uint32_t stn = sbase                                           \
            + (uint32_t)(((kt + 1) % STAGES) * STAGE_B);                     \
        if (kt == 0) LDFRAG(0, 0, st);                                       \
        _Pragma("unroll")                                                    \
        for (int ks = 0; ks < 4; ks++) {                                     \
            if (ks < 3) LDFRAG((ks + 1) & 1, ks + 1, st);                    \
            else if (kt + 1 < NKT) LDFRAG(0, 0, stn);                        \
            MMA_STEP(ks & 1);                                                \
        }                                                                    \
    }

// ---------------------------------------------------------------------------
// GEMM1 fused with activation. CTA 128 tokens x 64 act cols; warps 2Mx2N.
// B tile n 0-63 = gate cols, n 64-127 = up cols (+2048 in W1).
// ---------------------------------------------------------------------------
__global__ void __launch_bounds__(128, 2)
gemm1_act(const __half* __restrict__ X, const __half* __restrict__ W1h,
          __half* __restrict__ Act)
{
    extern __shared__ __align__(16) char smem[];
    const int tid = threadIdx.x;
    const int wid = tid >> 5, lane = tid & 31;
    const int g = lane >> 2, tg = lane & 3;
    const int wm = wid & 1, wn = wid >> 1;
    const int nt = blockIdx.x, tt = blockIdx.y, e = blockIdx.z;

    const __half* Ag = X + (size_t)(e * 1024 + tt * 128) * KD;
    const uint32_t sbase = smem_u32(smem);

    const int cr = tid >> 3, cc = tid & 7;          // A: 16 rows/pass
    const uint32_t cdstA = (uint32_t)(cr * ROW_A + cc * 16);
    const int cr2 = tid >> 4, cc2 = tid & 15;       // B: 8 k-rows/pass
    const uint32_t cdstB = (uint32_t)(cr2 * ROW_BB + cc2 * 16);
    const int ncol = nt * 64 + (cc2 & 7) * 8 + ((cc2 >= 8) ? 2048 : 0);
    const __half* Bg = W1h + (size_t)e * KD * 4096 + ncol;

    auto load_stage = [&](int buf, int kt) {
        const uint32_t sa = sbase + (uint32_t)buf * STAGE_B;
        const uint32_t sb = sa + TILE_A;
        const __half* a = Ag + kt * 64;
#pragma unroll
        for (int j = 0; j < 8; j++)
            CP16(sa + cdstA + (uint32_t)(j * 16 * ROW_A),
                 a + (size_t)(cr + j * 16) * KD + cc * 8);
        const __half* b = Bg + (size_t)(kt * 64 + cr2) * 4096;
#pragma unroll
        for (int j = 0; j < 8; j++)
            CP16(sb + cdstB + (uint32_t)(j * 8 * ROW_BB),
                 b + (size_t)(j * 8) * 4096);
        CP_COMMIT();
    };

    const uint32_t abase = (uint32_t)(wm * 64 * ROW_A) + ldsm_offA(lane);
    const uint32_t bbase = (uint32_t)(wn * 128) + ldsm_offB_T(lane) + TILE_A;

    float acc[4][8][4];
#pragma unroll
    for (int mi = 0; mi < 4; mi++)
#pragma unroll
        for (int ni = 0; ni < 8; ni++)
#pragma unroll
            for (int q = 0; q < 4; q++) acc[mi][ni][q] = 0.f;

    uint32_t af[2][4][4], bf[2][8][2];
    constexpr int NKT = KD / 64;   // 32
    MAINLOOP();

    // ---- fused act epilogue (stride 66 f32, 8B-aligned float2) ----------
    __syncthreads();
    float* ex = reinterpret_cast<float*>(smem) + wm * (64 * 66);
    if (wn == 1) {                         // up warps publish
#pragma unroll
        for (int mi = 0; mi < 4; mi++) {
            const int r0 = mi * 16 + g;
#pragma unroll
            for (int ni = 0; ni < 8; ni++) {
                const int cb = ni * 8 + tg * 2;
                *reinterpret_cast<float2*>(ex + r0 * 66 + cb) =
                    make_float2(acc[mi][ni][0], acc[mi][ni][1]);
                *reinterpret_cast<float2*>(ex + (r0 + 8) * 66 + cb) =
                    make_float2(acc[mi][ni][2], acc[mi][ni][3]);
            }
        }
    }
    __syncthreads();
    if (wn == 0) {                         // gate warps combine + store
        __half* Og = Act + (size_t)(e * 1024 + tt * 128 + wm * 64) * 2048
                   + nt * 64;
#pragma unroll
        for (int mi = 0; mi < 4; mi++) {
            const int r0 = mi * 16 + g;
#pragma unroll
            for (int ni = 0; ni < 8; ni++) {
                const int cb = ni * 8 + tg * 2;
                const float2 ulo = *reinterpret_cast<float2*>(ex + r0 * 66 + cb);
                const float2 uhi =
                    *reinterpret_cast<float2*>(ex + (r0 + 8) * 66 + cb);
                __half2 lo = __floats2half2_rn(
                    ulo.x * fmaxf(acc[mi][ni][0], 0.f),
                    ulo.y * fmaxf(acc[mi][ni][1], 0.f));
                __half2 hi = __floats2half2_rn(
                    uhi.x * fmaxf(acc[mi][ni][2], 0.f),
                    uhi.y * fmaxf(acc[mi][ni][3], 0.f));
                *reinterpret_cast<uint32_t*>(Og + (size_t)r0 * 2048 + cb) =
                    *reinterpret_cast<uint32_t*>(&lo);
                *reinterpret_cast<uint32_t*>(Og + (size_t)(r0 + 8) * 2048 + cb) =
                    *reinterpret_cast<uint32_t*>(&hi);
            }
        }
    }
}

// ---------------------------------------------------------------------------
// GEMM2: 128x128 CTA tile, warps 2Mx2N, fp32 out.
// ---------------------------------------------------------------------------
__global__ void __launch_bounds__(128, 2)
gemm2(const __half* __restrict__ X, const __half* __restrict__ W2h,
      float* __restrict__ C)
{
    extern __shared__ __align__(16) char smem[];
    const int tid = threadIdx.x;
    const int wid = tid >> 5, lane = tid & 31;
    const int g = lane >> 2, tg = lane & 3;
    const int wm = wid & 1, wn = wid >> 1;
    const int nt = blockIdx.x, tt = blockIdx.y, e = blockIdx.z;
    constexpr int WN = 2048;

    const __half* Ag = X + (size_t)(e * 1024 + tt * 128) * KD;
    const uint32_t sbase = smem_u32(smem);

    const int cr = tid >> 3, cc = tid & 7;
    const uint32_t cdstA = (uint32_t)(cr * ROW_A + cc * 16);
    const int cr2 = tid >> 4, cc2 = tid & 15;
    const uint32_t cdstB = (uint32_t)(cr2 * ROW_BB + cc2 * 16);
    const __half* Bg = W2h + (size_t)e * KD * WN + nt * 128 + cc2 * 8;

    auto load_stage = [&](int buf, int kt) {
        const uint32_t sa = sbase + (uint32_t)buf * STAGE_B;
        const uint32_t sb = sa + TILE_A;
        const __half* a = Ag + kt * 64;
#pragma unroll
        for (int j = 0; j < 8; j++)
            CP16(sa + cdstA + (uint32_t)(j * 16 * ROW_A),
                 a + (size_t)(cr + j * 16) * KD + cc * 8);
        const __half* b = Bg + (size_t)(kt * 64 + cr2) * WN;
#pragma unroll
        for (int j = 0; j < 8; j++)
            CP16(sb + cdstB + (uint32_t)(j * 8 * ROW_BB),
                 b + (size_t)(j * 8) * WN);
        CP_COMMIT();
    };

    const uint32_t abase = (uint32_t)(wm * 64 * ROW_A) + ldsm_offA(lane);
    const uint32_t bbase = (uint32_t)(wn * 128) + ldsm_offB_T(lane) + TILE_A;

    float acc[4][8][4];
#pragma unroll
    for (int mi = 0; mi < 4; mi++)
#pragma unroll
        for (int ni = 0; ni < 8; ni++)
#pragma unroll
            for (int q = 0; q < 4; q++) acc[mi][ni][q] = 0.f;

    uint32_t af[2][4][4], bf[2][8][2];
    constexpr int NKT = KD / 64;   // 32
    MAINLOOP();

    float* Cg = C + (size_t)(e * 1024 + tt * 128) * WN + nt * 128;
#pragma unroll
    for (int mi = 0; mi < 4; mi++) {
        const int r0 = wm * 64 + mi * 16 + g;
#pragma unroll
        for (int ni = 0; ni < 8; ni++) {
            const int cb = wn * 64 + ni * 8 + tg * 2;
            float2 lo = make_float2(acc[mi][ni][0], acc[mi][ni][1]);
            float2 hi = make_float2(acc[mi][ni][2], acc[mi][ni][3]);
            *reinterpret_cast<float2*>(Cg + (size_t)r0 * WN + cb) = lo;
            *reinterpret_cast<float2*>(Cg + (size_t)(r0 + 8) * WN + cb) = hi;
        }
    }
}

__global__ void __launch_bounds__(256)
round_f16_k(__half* __restrict__ dst, const float* __restrict__ src)
{
    const size_t i = ((size_t)blockIdx.x * blockDim.x + threadIdx.x) * 4;
    const float4 v = *reinterpret_cast<const float4*>(src + i);
    __half2 lo = __floats2half2_rn(v.x, v.y);
    __half2 hi = __floats2half2_rn(v.z, v.w);
    uint2 o = make_uint2(*reinterpret_cast<uint32_t*>(&lo),
                         *reinterpret_cast<uint32_t*>(&hi));
    *reinterpret_cast<uint2*>(dst + i) = o;
}

extern "C" void kernel_launch(void* const* d_in, const int* in_sizes, int n_in,
                              void* d_out, int out_size) {
    (void)in_sizes; (void)n_in; (void)out_size;
    const float* h  = (const float*)d_in[0];
    const float* w1 = (const float*)d_in[1];
    const float* w2 = (const float*)d_in[2];
    float* out = (float*)d_out;

    __half *act, *hh, *w1h, *w2h;
    cudaGetSymbolAddress((void**)&act, g_act);
    cudaGetSymbolAddress((void**)&hh,  g_hh);
    cudaGetSymbolAddress((void**)&w1h, g_w1h);
    cudaGetSymbolAddress((void**)&w2h, g_w2h);

    cudaFuncSetAttribute(gemm1_act,
                         cudaFuncAttributeMaxDynamicSharedMemorySize, SMEM_TOTAL);
    cudaFuncSetAttribute(gemm2,
                         cudaFuncAttributeMaxDynamicSharedMemorySize, SMEM_TOTAL);

    round_f16_k<<<(8192ull * 2048 / 4) / 256, 256>>>(hh, h);
    round_f16_k<<<(8ull * 2048 * 4096 / 4) / 256, 256>>>(w1h, w1);
    round_f16_k<<<(8ull * 2048 * 2048 / 4) / 256, 256>>>(w2h, w2);

    gemm1_act<<<dim3(32, 8, 8), 128, SMEM_TOTAL>>>(hh, w1h, act);
    gemm2<<<dim3(16, 8, 8), 128, SMEM_TOTAL>>>(act, w2h, out);
}